// round 2
// baseline (speedup 1.0000x reference)
#include <cuda_runtime.h>
#include <cuda_bf16.h>
#include <mma.h>

using namespace nvcuda;

#define D_MODEL 1024
#define BATCH   4
#define SEQ     4096
#define M_TOTAL (BATCH*SEQ)

#define CHUNK  128
#define NCHUNK (SEQ/CHUNK)   // 32

// Scratch (allocation-free rule: __device__ globals)
__device__ float g_u[(size_t)M_TOTAL * D_MODEL];
__device__ float g_h[(size_t)M_TOTAL * D_MODEL];
__device__ float g_C  [BATCH*NCHUNK*D_MODEL];
__device__ float g_cin[BATCH*NCHUNK*D_MODEL];

// ---------------- TF32 wmma GEMM:  out[m,n] = (sum_d A[m,d]*W[n,d] + bias[n]) * mask?[m]
#define BM 128
#define BN 128
#define BK 32
#define LDT 40    // smem tile row stride (floats), 160B rows keep float4 alignment
#define LDC 136   // epilogue staging row stride

__global__ __launch_bounds__(256, 2)
void gemm_nt(const float* __restrict__ A, const float* __restrict__ W,
             const float* __restrict__ bias, const float* __restrict__ mask,
             float* __restrict__ out)
{
    __shared__ float smem[2 * BM * LDT];      // 40960 B
    float* As = smem;
    float* Bs = smem + BM * LDT;
    float* Cs = smem;                          // reused for epilogue (64*LDC=8704 floats)

    const int tid    = threadIdx.x;
    const int warp   = tid >> 5;
    const int warp_m = warp & 3;   // 4 tiles of 32 rows
    const int warp_n = warp >> 2;  // 2 tiles of 64 cols
    const int m0 = blockIdx.y * BM;
    const int n0 = blockIdx.x * BN;

    wmma::fragment<wmma::accumulator, 16, 16, 8, float> acc[2][4];
    #pragma unroll
    for (int i = 0; i < 2; i++)
        #pragma unroll
        for (int j = 0; j < 4; j++)
            wmma::fill_fragment(acc[i][j], 0.0f);

    for (int k0 = 0; k0 < D_MODEL; k0 += BK) {
        // Load A tile [128x32] and W tile [128x32] as float4 (4 per thread each)
        #pragma unroll
        for (int i = 0; i < 4; i++) {
            int idx = tid + i * 256;           // 0..1023
            int r = idx >> 3;                  // row 0..127
            int c = (idx & 7) << 2;            // col 0,4,...,28
            float4 va = *(const float4*)(A + (size_t)(m0 + r) * D_MODEL + k0 + c);
            *(float4*)(As + r * LDT + c) = va;
            float4 vw = *(const float4*)(W + (size_t)(n0 + r) * D_MODEL + k0 + c);
            *(float4*)(Bs + r * LDT + c) = vw;
        }
        __syncthreads();

        #pragma unroll
        for (int kk = 0; kk < BK; kk += 8) {
            wmma::fragment<wmma::matrix_a, 16, 16, 8, wmma::precision::tf32, wmma::row_major> af[2];
            wmma::fragment<wmma::matrix_b, 16, 16, 8, wmma::precision::tf32, wmma::col_major> bf[4];
            #pragma unroll
            for (int i = 0; i < 2; i++) {
                wmma::load_matrix_sync(af[i], As + (warp_m * 32 + i * 16) * LDT + kk, LDT);
                #pragma unroll
                for (int t = 0; t < af[i].num_elements; t++)
                    af[i].x[t] = wmma::__float_to_tf32(af[i].x[t]);
            }
            #pragma unroll
            for (int j = 0; j < 4; j++) {
                wmma::load_matrix_sync(bf[j], Bs + (warp_n * 64 + j * 16) * LDT + kk, LDT);
                #pragma unroll
                for (int t = 0; t < bf[j].num_elements; t++)
                    bf[j].x[t] = wmma::__float_to_tf32(bf[j].x[t]);
            }
            #pragma unroll
            for (int i = 0; i < 2; i++)
                #pragma unroll
                for (int j = 0; j < 4; j++)
                    wmma::mma_sync(acc[i][j], af[i], bf[j], acc[i][j]);
        }
        __syncthreads();
    }

    // Epilogue in two 64-row stages through smem (adds bias, applies optional mask)
    #pragma unroll
    for (int stage = 0; stage < 2; stage++) {
        if ((warp_m >> 1) == stage) {
            int rbase = (warp_m & 1) * 32;
            #pragma unroll
            for (int i = 0; i < 2; i++)
                #pragma unroll
                for (int j = 0; j < 4; j++)
                    wmma::store_matrix_sync(Cs + (rbase + i * 16) * LDC + warp_n * 64 + j * 16,
                                            acc[i][j], LDC, wmma::mem_row_major);
        }
        __syncthreads();
        #pragma unroll
        for (int i = 0; i < 32; i++) {
            int idx = tid + i * 256;           // 0..8191
            int r = idx >> 7;                  // 0..63
            int c = idx & 127;
            int gm = m0 + stage * 64 + r;
            int gn = n0 + c;
            float v = Cs[r * LDC + c] + bias[gn];
            if (mask) v *= mask[gm];
            out[(size_t)gm * D_MODEL + gn] = v;
        }
        __syncthreads();
    }
}

// ---------------- Decay scan (h_t = decay*h_{t-1} + u_t), chunked 3-pass
__device__ __forceinline__ float get_decay(const float* dp) {
    return 1.0f / (1.0f + expf(-dp[0]));
}

// Pass 1: per-chunk local end value (scan seeded with 0), no intermediate stores.
__global__ void scan_pass1(const float* __restrict__ dp)
{
    float decay = get_decay(dp);
    int e = blockIdx.x * 256 + threadIdx.x;   // 0..1023
    int c = blockIdx.y;                       // chunk
    int b = blockIdx.z;                       // batch
    const float* u = g_u + ((size_t)(b * SEQ + c * CHUNK)) * D_MODEL + e;
    float h = 0.0f;
    #pragma unroll 4
    for (int s = 0; s < CHUNK; s++)
        h = fmaf(decay, h, u[(size_t)s * D_MODEL]);
    g_C[((size_t)b * NCHUNK + c) * D_MODEL + e] = h;
}

// Pass 2: combine chunk carries serially per (b,e). decay^CHUNK via 7 squarings (exact path).
__global__ void scan_pass2(const float* __restrict__ dp)
{
    float decay = get_decay(dp);
    float dpow = decay;
    #pragma unroll
    for (int i = 0; i < 7; i++) dpow *= dpow;  // decay^128
    int idx = blockIdx.x * 256 + threadIdx.x;  // 0..4095
    int b = idx >> 10;
    int e = idx & 1023;
    float he = 0.0f;
    #pragma unroll 4
    for (int c = 0; c < NCHUNK; c++) {
        size_t off = ((size_t)b * NCHUNK + c) * D_MODEL + e;
        g_cin[off] = he;
        he = fmaf(dpow, he, g_C[off]);
    }
}

// Pass 3: re-scan each chunk seeded with its carry-in; write full h.
__global__ void scan_pass3(const float* __restrict__ dp)
{
    float decay = get_decay(dp);
    int e = blockIdx.x * 256 + threadIdx.x;
    int c = blockIdx.y;
    int b = blockIdx.z;
    size_t base = ((size_t)(b * SEQ + c * CHUNK)) * D_MODEL + e;
    const float* u = g_u + base;
    float*       h = g_h + base;
    float acc = g_cin[((size_t)b * NCHUNK + c) * D_MODEL + e];
    #pragma unroll 4
    for (int s = 0; s < CHUNK; s++) {
        acc = fmaf(decay, acc, u[(size_t)s * D_MODEL]);
        h[(size_t)s * D_MODEL] = acc;
    }
}

// ---------------- launch
extern "C" void kernel_launch(void* const* d_in, const int* in_sizes, int n_in,
                              void* d_out, int out_size)
{
    const float* x     = (const float*)d_in[0];
    const float* mask  = (const float*)d_in[1];
    const float* W_up  = (const float*)d_in[2];
    const float* b_up  = (const float*)d_in[3];
    const float* W_f   = (const float*)d_in[4];
    const float* b_f   = (const float*)d_in[5];
    const float* dp    = (const float*)d_in[6];
    float* out = (float*)d_out;

    float *u_ptr, *h_ptr;
    cudaGetSymbolAddress((void**)&u_ptr, g_u);
    cudaGetSymbolAddress((void**)&h_ptr, g_h);

    dim3 ggrid(D_MODEL / BN, M_TOTAL / BM);   // (8, 128)

    gemm_nt<<<ggrid, 256>>>(x, W_up, b_up, mask, u_ptr);
    scan_pass1<<<dim3(4, NCHUNK, BATCH), 256>>>(dp);
    scan_pass2<<<16, 256>>>(dp);
    scan_pass3<<<dim3(4, NCHUNK, BATCH), 256>>>(dp);
    gemm_nt<<<ggrid, 256>>>(h_ptr, W_f, b_f, nullptr, out);
}

// round 6
// speedup vs baseline: 1.0255x; 1.0255x over previous
#include <cuda_runtime.h>
#include <mma.h>
#include <cstdint>

using namespace nvcuda;

#define D_MODEL 1024
#define BATCH   4
#define SEQ     4096
#define M_TOTAL (BATCH*SEQ)

#define CHUNK  64
#define NCHUNK (SEQ/CHUNK)   // 64

// Scratch (allocation-free rule: __device__ globals)
__device__ float g_u[(size_t)M_TOTAL * D_MODEL];
__device__ float g_h[(size_t)M_TOTAL * D_MODEL];
__device__ float g_C  [BATCH*NCHUNK*D_MODEL];
__device__ float g_cin[BATCH*NCHUNK*D_MODEL];

// ======================= helpers =======================
__device__ __forceinline__ uint32_t smem_u32(const void* p) {
    uint32_t a;
    asm("{ .reg .u64 t; cvta.to.shared.u64 t, %1; cvt.u32.u64 %0, t; }" : "=r"(a) : "l"(p));
    return a;
}
#define CP_ASYNC16(smem_addr, gptr) \
    asm volatile("cp.async.cg.shared.global [%0], [%1], 16;" :: "r"(smem_addr), "l"(gptr))
#define CP_COMMIT() asm volatile("cp.async.commit_group;" ::: "memory")
#define CP_WAIT(n)  asm volatile("cp.async.wait_group %0;" :: "n"(n) : "memory")

// ======================= tf32 wmma GEMM, 3-stage cp.async pipeline
// out[m,n] = (sum_d A[m,d]*W[n,d] + bias[n]) * mask?[m]
#define BM 128
#define BN 128
#define BK 16
#define LDT 20        // padded row stride (floats) for [128 x 16] tiles
#define STAGES 3
#define TILE_FLOATS (128 * LDT)            // one matrix tile in smem
#define STAGE_FLOATS (2 * TILE_FLOATS)     // A + B
#define SMEM_BYTES (STAGES * STAGE_FLOATS * 4)   // 61440
#define LDC 136       // epilogue staging stride
#define KITERS (D_MODEL / BK)              // 64

extern __shared__ float g_smem[];

__global__ __launch_bounds__(256, 2)
void gemm_tc(const float* __restrict__ A, const float* __restrict__ W,
             const float* __restrict__ bias, const float* __restrict__ mask,
             float* __restrict__ out)
{
    const int tid    = threadIdx.x;
    const int warp   = tid >> 5;
    const int warp_m = warp & 3;   // 4 row-tiles of 32
    const int warp_n = warp >> 2;  // 2 col-tiles of 64
    const int m0 = blockIdx.y * BM;
    const int n0 = blockIdx.x * BN;

    const uint32_t s_base = smem_u32(g_smem);

    // Per-thread load coordinates: 512 float4 per matrix per stage, 2 per thread.
    // idx = tid + j*256 ; r = idx>>2 (0..127) ; c4 = (idx&3)*4
    const int r_ld [2] = { (tid + 0)   >> 2, (tid + 256) >> 2 };
    const int c4_ld[2] = { ((tid + 0) & 3) << 2, ((tid + 256) & 3) << 2 };

    auto issue_loads = [&](int kiter, int buf) {
        const int k0 = kiter * BK;
        const uint32_t sa = s_base + (uint32_t)(buf * STAGE_FLOATS) * 4u;
        const uint32_t sb = sa + TILE_FLOATS * 4u;
        #pragma unroll
        for (int j = 0; j < 2; j++) {
            int r = r_ld[j], c4 = c4_ld[j];
            uint32_t so = (uint32_t)(r * LDT + c4) * 4u;
            CP_ASYNC16(sa + so, A + (size_t)(m0 + r) * D_MODEL + k0 + c4);
            CP_ASYNC16(sb + so, W + (size_t)(n0 + r) * D_MODEL + k0 + c4);
        }
    };

    wmma::fragment<wmma::accumulator, 16, 16, 8, float> acc[2][4];
    #pragma unroll
    for (int i = 0; i < 2; i++)
        #pragma unroll
        for (int j = 0; j < 4; j++)
            wmma::fill_fragment(acc[i][j], 0.0f);

    // Prologue: stages 0 .. STAGES-2
    #pragma unroll
    for (int s = 0; s < STAGES - 1; s++) {
        issue_loads(s, s);
        CP_COMMIT();
    }

    for (int i = 0; i < KITERS; i++) {
        CP_WAIT(STAGES - 2);
        __syncthreads();

        // Prefetch iter i+STAGES-1 into the buffer freed at iter i-1
        if (i + STAGES - 1 < KITERS)
            issue_loads(i + STAGES - 1, (i + STAGES - 1) % STAGES);
        CP_COMMIT();

        const int buf = i % STAGES;
        const float* As = g_smem + buf * STAGE_FLOATS;
        const float* Bs = As + TILE_FLOATS;

        #pragma unroll
        for (int kk = 0; kk < BK; kk += 8) {
            wmma::fragment<wmma::matrix_a, 16, 16, 8, wmma::precision::tf32, wmma::row_major> af[2];
            wmma::fragment<wmma::matrix_b, 16, 16, 8, wmma::precision::tf32, wmma::col_major> bf[4];
            #pragma unroll
            for (int a = 0; a < 2; a++) {
                wmma::load_matrix_sync(af[a], As + (warp_m * 32 + a * 16) * LDT + kk, LDT);
                #pragma unroll
                for (int t = 0; t < af[a].num_elements; t++)
                    af[a].x[t] = wmma::__float_to_tf32(af[a].x[t]);
            }
            #pragma unroll
            for (int b = 0; b < 4; b++) {
                wmma::load_matrix_sync(bf[b], Bs + (warp_n * 64 + b * 16) * LDT + kk, LDT);
                #pragma unroll
                for (int t = 0; t < bf[b].num_elements; t++)
                    bf[b].x[t] = wmma::__float_to_tf32(bf[b].x[t]);
            }
            #pragma unroll
            for (int a = 0; a < 2; a++)
                #pragma unroll
                for (int b = 0; b < 4; b++)
                    wmma::mma_sync(acc[a][b], af[a], bf[b], acc[a][b]);
        }
    }
    __syncthreads();   // all warps done with smem tiles before epilogue reuse

    // Epilogue: two 64-row stages through smem; fuse bias + optional mask.
    float* Cs = g_smem;
    #pragma unroll
    for (int stage = 0; stage < 2; stage++) {
        if ((warp_m >> 1) == stage) {
            int rbase = (warp_m & 1) * 32;
            #pragma unroll
            for (int a = 0; a < 2; a++)
                #pragma unroll
                for (int b = 0; b < 4; b++)
                    wmma::store_matrix_sync(Cs + (rbase + a * 16) * LDC + warp_n * 64 + b * 16,
                                            acc[a][b], LDC, wmma::mem_row_major);
        }
        __syncthreads();
        #pragma unroll
        for (int it = 0; it < 8; it++) {
            int idx = (tid + it * 256) << 2;   // float4 granularity: 0..8188
            int r = idx >> 7;                  // 0..63
            int c = idx & 127;
            int gm = m0 + stage * 64 + r;
            int gn = n0 + c;
            float4 v = *(const float4*)(Cs + r * LDC + c);
            float4 bb = *(const float4*)(bias + gn);
            float mv = mask ? mask[gm] : 1.0f;
            v.x = (v.x + bb.x) * mv;
            v.y = (v.y + bb.y) * mv;
            v.z = (v.z + bb.z) * mv;
            v.w = (v.w + bb.w) * mv;
            *(float4*)(out + (size_t)gm * D_MODEL + gn) = v;
        }
        __syncthreads();
    }
}

// ---------------- Decay scan (h_t = decay*h_{t-1} + u_t), chunked 3-pass
__device__ __forceinline__ float get_decay(const float* dp) {
    return 1.0f / (1.0f + expf(-dp[0]));
}

__global__ __launch_bounds__(256) void scan_pass1(const float* __restrict__ dp)
{
    float decay = get_decay(dp);
    int e = blockIdx.x * 256 + threadIdx.x;   // 0..1023
    int c = blockIdx.y;                       // chunk
    int b = blockIdx.z;                       // batch
    const float* u = g_u + ((size_t)(b * SEQ + c * CHUNK)) * D_MODEL + e;
    float h = 0.0f;
    #pragma unroll 8
    for (int s = 0; s < CHUNK; s++)
        h = fmaf(decay, h, u[(size_t)s * D_MODEL]);
    g_C[((size_t)b * NCHUNK + c) * D_MODEL + e] = h;
}

__global__ __launch_bounds__(256) void scan_pass2(const float* __restrict__ dp)
{
    float decay = get_decay(dp);
    float dpow = decay;
    #pragma unroll
    for (int i = 0; i < 6; i++) dpow *= dpow;  // decay^64 (CHUNK=64)
    int idx = blockIdx.x * 256 + threadIdx.x;  // 0..4095
    int b = idx >> 10;
    int e = idx & 1023;
    float he = 0.0f;
    #pragma unroll 4
    for (int c = 0; c < NCHUNK; c++) {
        size_t off = ((size_t)b * NCHUNK + c) * D_MODEL + e;
        g_cin[off] = he;
        he = fmaf(dpow, he, g_C[off]);
    }
}

__global__ __launch_bounds__(256) void scan_pass3(const float* __restrict__ dp)
{
    float decay = get_decay(dp);
    int e = blockIdx.x * 256 + threadIdx.x;
    int c = blockIdx.y;
    int b = blockIdx.z;
    size_t base = ((size_t)(b * SEQ + c * CHUNK)) * D_MODEL + e;
    const float* u = g_u + base;
    float*       h = g_h + base;
    float acc = g_cin[((size_t)b * NCHUNK + c) * D_MODEL + e];
    #pragma unroll 8
    for (int s = 0; s < CHUNK; s++) {
        acc = fmaf(decay, acc, u[(size_t)s * D_MODEL]);
        h[(size_t)s * D_MODEL] = acc;
    }
}

// ---------------- launch
extern "C" void kernel_launch(void* const* d_in, const int* in_sizes, int n_in,
                              void* d_out, int out_size)
{
    const float* x     = (const float*)d_in[0];
    const float* mask  = (const float*)d_in[1];
    const float* W_up  = (const float*)d_in[2];
    const float* b_up  = (const float*)d_in[3];
    const float* W_f   = (const float*)d_in[4];
    const float* b_f   = (const float*)d_in[5];
    const float* dp    = (const float*)d_in[6];
    float* out = (float*)d_out;

    float *u_ptr, *h_ptr;
    cudaGetSymbolAddress((void**)&u_ptr, g_u);
    cudaGetSymbolAddress((void**)&h_ptr, g_h);

    cudaFuncSetAttribute(gemm_tc, cudaFuncAttributeMaxDynamicSharedMemorySize, SMEM_BYTES);

    dim3 ggrid(D_MODEL / BN, M_TOTAL / BM);   // (8, 128)

    gemm_tc<<<ggrid, 256, SMEM_BYTES>>>(x, W_up, b_up, mask, u_ptr);
    scan_pass1<<<dim3(4, NCHUNK, BATCH), 256>>>(dp);
    scan_pass2<<<16, 256>>>(dp);
    scan_pass3<<<dim3(4, NCHUNK, BATCH), 256>>>(dp);
    gemm_tc<<<ggrid, 256, SMEM_BYTES>>>(h_ptr, W_f, b_f, nullptr, out);
}